// round 6
// baseline (speedup 1.0000x reference)
#include <cuda_runtime.h>
#include <cuda_bf16.h>
#include <cstdint>

// RNN-T joint network, 2 launches:
//  1) convert: fp32 -> bf16 (hi,lo) split images; block 0 zeroes flags.
//  2) fused persistent kernel, grid = 296 = ALL co-resident (1 wave):
//       bid 0..147   : GEMM workers. 640 tiles (128 pred + 512 enc) of
//                      64x64, K=1536, mma.sync bf16, 3-stage cp.async,
//                      SW128 smem. Publish tiles via release flags.
//       bid 148..295 : ADD workers. 512 items (1 MB output each), each
//                      waits on 1 enc tile + 1 pred tile, pred+bias in
//                      smem, streams output with st.global.cs.
//     Output drain overlaps GEMM compute; no slot starvation possible.

#define VOCAB 2048
#define KC    1536
#define NB    4
#define NT    256
#define NU    64
#define NWORK 148
#define GRID  296

// -------- scratch (device globals; no allocations allowed) --------
__device__ __nv_bfloat16 g_Ac[1280 * KC];
__device__ __nv_bfloat16 g_Be[VOCAB * KC];
__device__ __nv_bfloat16 g_Bp[VOCAB * KC];
__device__ float g_enc [1024 * VOCAB];
__device__ float g_pred[ 256 * VOCAB];
__device__ int   g_flags[640];   // [0,128): pred tile pb*32+n ; [128,640): enc 128+m*32+n

// ---------------------------------------------------------------------------
// Stage 1: split-precision convert (proven) + flag reset in block 0
// ---------------------------------------------------------------------------
__global__ __launch_bounds__(256)
void convert_kernel(const float* __restrict__ enc,
                    const float* __restrict__ pred,
                    const float* __restrict__ W) {
    if (blockIdx.x == 0) {
        for (int t = threadIdx.x; t < 640; t += 256) g_flags[t] = 0;
    }
    int idx = blockIdx.x * 256 + threadIdx.x;

    float2 x;
    __nv_bfloat16* base;
    bool isA;
    if (idx < 262144) {
        x = ((const float2*)enc)[idx];
        int m = idx >> 8, k = (idx & 255) * 2;
        base = g_Ac + (size_t)m * KC + k;
        isA = true;
    } else if (idx < 327680) {
        int p = idx - 262144;
        x = ((const float2*)pred)[p];
        int m = 1024 + (p >> 8), k = (p & 255) * 2;
        base = g_Ac + (size_t)m * KC + k;
        isA = true;
    } else {
        int p = idx - 327680;
        x = ((const float2*)W)[p];
        int v = p >> 9, k = (p & 511) * 2;
        if (k < 512) base = g_Be + (size_t)v * KC + k;
        else         base = g_Bp + (size_t)v * KC + (k - 512);
        isA = false;
    }

    __nv_bfloat162 h, l;
    h.x = __float2bfloat16_rn(x.x);
    h.y = __float2bfloat16_rn(x.y);
    l.x = __float2bfloat16_rn(x.x - __bfloat162float(h.x));
    l.y = __float2bfloat16_rn(x.y - __bfloat162float(h.y));

    if (isA) {  // [hi | hi | lo]
        *(__nv_bfloat162*)(base)        = h;
        *(__nv_bfloat162*)(base +  512) = h;
        *(__nv_bfloat162*)(base + 1024) = l;
    } else {    // [hi | lo | hi]
        *(__nv_bfloat162*)(base)        = h;
        *(__nv_bfloat162*)(base +  512) = l;
        *(__nv_bfloat162*)(base + 1024) = h;
    }
}

// ---------------------------------------------------------------------------
// helpers
// ---------------------------------------------------------------------------
#define BK     64
#define STAGES 3
#define A_ST   8192                   // 64 rows * 128B
#define B_ST   8192                   // 64 rows * 128B
#define ST_SZ  (A_ST + B_ST)          // 16KB
#define DSMEM  (STAGES * ST_SZ)       // 48KB

__device__ __forceinline__ uint32_t s2u(const void* p) {
    return (uint32_t)__cvta_generic_to_shared(p);
}
#define CPA16(s, g) asm volatile("cp.async.cg.shared.global [%0], [%1], 16;" :: "r"(s), "l"(g))
#define LDSM4(r0,r1,r2,r3,a) asm volatile( \
    "ldmatrix.sync.aligned.m8n8.x4.shared.b16 {%0,%1,%2,%3}, [%4];" \
    : "=r"(r0),"=r"(r1),"=r"(r2),"=r"(r3) : "r"(a))
#define MMA16816(c,a0,a1,a2,a3,b0,b1) asm volatile( \
    "mma.sync.aligned.m16n8k16.row.col.f32.bf16.bf16.f32 " \
    "{%0,%1,%2,%3},{%4,%5,%6,%7},{%8,%9},{%0,%1,%2,%3};" \
    : "+f"(c[0]),"+f"(c[1]),"+f"(c[2]),"+f"(c[3]) \
    : "r"(a0),"r"(a1),"r"(a2),"r"(a3),"r"(b0),"r"(b1))

__device__ __forceinline__ uint32_t swz(uint32_t row, uint32_t cb) {
    return row * 128 + (cb ^ ((row & 7) * 16));
}
__device__ __forceinline__ void stcs(float4* p, float4 v) {
    asm volatile("st.global.cs.v4.f32 [%0], {%1,%2,%3,%4};"
                 :: "l"(p), "f"(v.x), "f"(v.y), "f"(v.z), "f"(v.w));
}
__device__ __forceinline__ void wait_flag(const int* f) {
    int v;
    while (true) {
        asm volatile("ld.acquire.gpu.global.b32 %0, [%1];" : "=r"(v) : "l"(f));
        if (v) break;
        __nanosleep(200);
    }
}

// ---------------------------------------------------------------------------
// Fused persistent kernel (296 CTAs, all resident).
// ---------------------------------------------------------------------------
__global__ __launch_bounds__(256, 2)
void fused_kernel(const float* __restrict__ bias, float* __restrict__ out) {
    extern __shared__ __align__(1024) char smem[];
    const int bid = blockIdx.x;
    const int tid = threadIdx.x;

    if (bid >= NWORK) {
        // ===================== ADD worker =====================
        float (*ps)[64] = (float(*)[64])smem;   // 64u x 64v fp32 = 16KB

        for (int j = bid - NWORK; j < 512; j += NWORK) {
            const int m = j >> 5, n = j & 31;
            const int b = m >> 2;
            const int tbase = (m & 3) * 64;
            const int vbase = n * 64;

            if (tid == 0) wait_flag(&g_flags[128 + j]);
            if (tid == 32) wait_flag(&g_flags[b * 32 + n]);
            __syncthreads();

            // pred chunk + bias -> smem (64u x 64v = 1024 float4, 4/thr)
            const float4* pr = (const float4*)(g_pred + (size_t)b * NU * VOCAB + vbase);
            const float4* bi = (const float4*)(bias + vbase);
            #pragma unroll
            for (int i = 0; i < 4; i++) {
                int e = tid + i * 256;
                int u = e >> 4, cc = e & 15;
                float4 p = pr[(size_t)u * (VOCAB / 4) + cc];
                float4 bv = bi[cc];
                ((float4*)ps[u])[cc] =
                    make_float4(p.x + bv.x, p.y + bv.y, p.z + bv.z, p.w + bv.w);
            }
            __syncthreads();

            const int v4 = tid & 15;       // v float4 index
            const int ug = tid >> 4;       // u group (4 u's each)
            const float4* eb = (const float4*)
                (g_enc + (size_t)(b * NT + tbase) * VOCAB + vbase);
            float4* ob = (float4*)
                (out + ((size_t)(b * NT + tbase) * NU) * VOCAB + vbase);

            for (int t = 0; t < 64; t++) {
                float4 e = eb[(size_t)t * (VOCAB / 4) + v4];
                #pragma unroll
                for (int us = 0; us < 4; us++) {
                    int u = ug * 4 + us;
                    float4 p = ((float4*)ps[u])[v4];
                    stcs(&ob[((size_t)t * NU + u) * (VOCAB / 4) + v4],
                         make_float4(e.x + p.x, e.y + p.y, e.z + p.z, e.w + p.w));
                }
            }
            __syncthreads();   // before reusing ps
        }
        return;
    }

    // ===================== GEMM worker =====================
    const uint32_t sb = s2u(smem);
    const int lane = tid & 31;
    const int wid  = tid >> 5;
    const int warp_m = wid & 3;     // 16 M rows each
    const int warp_n = wid >> 2;    // 32 N cols each

    // cp.async chunk precompute: A 512 chunks (2/thr), B 512 (2/thr)
    const int ra0 = tid >> 3,         ja0 = (tid & 7) * 16;
    const int ra1 = (tid + 256) >> 3, ja1 = (tid & 7) * 16;
    const uint32_t sA0 = swz(ra0, ja0), sA1 = swz(ra1, ja1);
    const uint32_t sB0 = sA0 + A_ST,    sB1 = sA1 + A_ST;

    // ldmatrix lane addresses (stage-relative)
    const int rowA = warp_m * 16 + (lane & 15);
    const uint32_t uA = swz(rowA, (lane >> 4) * 16);
    const int rowB0 = warp_n * 32 + ((lane >> 4) & 1) * 8 + (lane & 7);
    const uint32_t uB = swz(rowB0, ((lane >> 3) & 1) * 16) + A_ST;

    for (int item = bid; item < 640; item += NWORK) {
        const __nv_bfloat16* gA;
        const __nv_bfloat16* gB;
        float* C;
        int flag;
        if (item < 128) {                 // pred tile
            const int pb = item >> 5, n = item & 31;
            gA = g_Ac + (size_t)(1024 + pb * 64) * KC;
            gB = g_Bp + (size_t)(n * 64) * KC;
            C  = g_pred + (size_t)(pb * 64) * VOCAB + n * 64;
            flag = item;
        } else {                          // enc tile
            const int e = item - 128;
            const int m = e >> 5, n = e & 31;
            gA = g_Ac + (size_t)(m * 64) * KC;
            gB = g_Be + (size_t)(n * 64) * KC;
            C  = g_enc + (size_t)(m * 64) * VOCAB + n * 64;
            flag = item;
        }

        float c[2][4][4];
        #pragma unroll
        for (int i = 0; i < 2; i++)
            #pragma unroll
            for (int jj = 0; jj < 4; jj++)
                #pragma unroll
                for (int e2 = 0; e2 < 4; e2++) c[i][jj][e2] = 0.f;

        auto fill = [&](int s, int koff) {
            const uint32_t ab = sb + s * ST_SZ;
            CPA16(ab + sA0, gA + (size_t)ra0 * KC + koff + ja0 / 2);
            CPA16(ab + sA1, gA + (size_t)ra1 * KC + koff + ja1 / 2);
            CPA16(ab + sB0, gB + (size_t)ra0 * KC + koff + ja0 / 2);
            CPA16(ab + sB1, gB + (size_t)ra1 * KC + koff + ja1 / 2);
            asm volatile("cp.async.commit_group;");
        };

        fill(0, 0);
        fill(1, BK);

        const int NKT = KC / BK;   // 24
        int s = 0;
        for (int kt = 0; kt < NKT; kt++) {
            if (kt < NKT - 1) asm volatile("cp.async.wait_group 1;");
            else              asm volatile("cp.async.wait_group 0;");
            __syncthreads();

            if (kt + 2 < NKT) {
                int sn = s + 2; if (sn >= STAGES) sn -= STAGES;
                fill(sn, (kt + 2) * BK);
            }

            const uint32_t abase = sb + s * ST_SZ + uA;
            const uint32_t bbase = sb + s * ST_SZ + uB;
            #pragma unroll
            for (int kk = 0; kk < 4; kk++) {
                uint32_t a[4], b[2][4];
                LDSM4(a[0], a[1], a[2], a[3], abase ^ (kk << 5));
                #pragma unroll
                for (int nb = 0; nb < 2; nb++)
                    LDSM4(b[nb][0], b[nb][1], b[nb][2], b[nb][3],
                          (bbase + nb * 2048) ^ (kk << 5));
                MMA16816(c[0][0], a[0], a[1], a[2], a[3], b[0][0], b[0][1]);
                MMA16816(c[0][1], a[0], a[1], a[2], a[3], b[0][2], b[0][3]);
                MMA16816(c[0][2], a[0], a[1], a[2], a[3], b[1][0], b[1][1]);
                MMA16816(c[0][3], a[0], a[1], a[2], a[3], b[1][2], b[1][3]);
            }
            if (++s >= STAGES) s -= STAGES;
        }

        // epilogue: fp32 frags -> scratch
        const int mrow0 = warp_m * 16 + (lane >> 2);
        const int ncol0 = warp_n * 32 + (lane & 3) * 2;
        #pragma unroll
        for (int ni = 0; ni < 4; ni++) {
            float* p0 = &C[(size_t)(mrow0)     * VOCAB + ncol0 + ni * 8];
            float* p1 = &C[(size_t)(mrow0 + 8) * VOCAB + ncol0 + ni * 8];
            *(float2*)p0 = make_float2(c[0][ni][0], c[0][ni][1]);
            *(float2*)p1 = make_float2(c[0][ni][2], c[0][ni][3]);
        }

        __threadfence();
        __syncthreads();
        if (tid == 0) atomicExch(&g_flags[flag], 1);
    }
}

// ---------------------------------------------------------------------------
extern "C" void kernel_launch(void* const* d_in, const int* in_sizes, int n_in,
                              void* d_out, int out_size) {
    const float* enc  = (const float*)d_in[0];
    const float* pred = (const float*)d_in[1];
    const float* W    = (const float*)d_in[2];
    const float* bias = (const float*)d_in[3];
    float* out = (float*)d_out;

    cudaFuncSetAttribute(fused_kernel,
                         cudaFuncAttributeMaxDynamicSharedMemorySize, DSMEM);

    convert_kernel<<<5376, 256>>>(enc, pred, W);
    fused_kernel<<<GRID, 256, DSMEM>>>(bias, out);
}

// round 7
// speedup vs baseline: 1.3492x; 1.3492x over previous
#include <cuda_runtime.h>
#include <cuda_bf16.h>
#include <cstdint>

// RNN-T joint network, 2 launches:
//  1) convert: fp32 -> bf16 (hi,lo) split images; block 0 zeroes flags.
//  2) fused kernel, grid = 320 (one wave @ occ 2):
//       bid 0..63   : pred GEMM tile 64x128 -> g_pred, release flag.
//       bid 64..319 : enc GEMM tile 64x128 (mma.sync bf16, K=1536, 3-stage
//                     cp.async, SW128) -> smem; wait 1 pred flag; load pred
//                     tile + bias to smem; drain 2MB output brick with
//                     coalesced st.global.cs. No enc_proj global round trip.

#define VOCAB 2048
#define KC    1536
#define NB    4
#define NT    256
#define NU    64

// -------- scratch (device globals; no allocations allowed) --------
__device__ __nv_bfloat16 g_Ac[1280 * KC];
__device__ __nv_bfloat16 g_Be[VOCAB * KC];
__device__ __nv_bfloat16 g_Bp[VOCAB * KC];
__device__ float g_pred[256 * VOCAB];
__device__ int   g_flags[64];            // pred tile (pb, n): pb*16 + n

// ---------------------------------------------------------------------------
// Stage 1: split-precision convert (proven) + flag reset
// ---------------------------------------------------------------------------
__global__ __launch_bounds__(256)
void convert_kernel(const float* __restrict__ enc,
                    const float* __restrict__ pred,
                    const float* __restrict__ W) {
    if (blockIdx.x == 0 && threadIdx.x < 64) g_flags[threadIdx.x] = 0;
    int idx = blockIdx.x * 256 + threadIdx.x;

    float2 x;
    __nv_bfloat16* base;
    bool isA;
    if (idx < 262144) {
        x = ((const float2*)enc)[idx];
        int m = idx >> 8, k = (idx & 255) * 2;
        base = g_Ac + (size_t)m * KC + k;
        isA = true;
    } else if (idx < 327680) {
        int p = idx - 262144;
        x = ((const float2*)pred)[p];
        int m = 1024 + (p >> 8), k = (p & 255) * 2;
        base = g_Ac + (size_t)m * KC + k;
        isA = true;
    } else {
        int p = idx - 327680;
        x = ((const float2*)W)[p];
        int v = p >> 9, k = (p & 511) * 2;
        if (k < 512) base = g_Be + (size_t)v * KC + k;
        else         base = g_Bp + (size_t)v * KC + (k - 512);
        isA = false;
    }

    __nv_bfloat162 h, l;
    h.x = __float2bfloat16_rn(x.x);
    h.y = __float2bfloat16_rn(x.y);
    l.x = __float2bfloat16_rn(x.x - __bfloat162float(h.x));
    l.y = __float2bfloat16_rn(x.y - __bfloat162float(h.y));

    if (isA) {  // [hi | hi | lo]
        *(__nv_bfloat162*)(base)        = h;
        *(__nv_bfloat162*)(base +  512) = h;
        *(__nv_bfloat162*)(base + 1024) = l;
    } else {    // [hi | lo | hi]
        *(__nv_bfloat162*)(base)        = h;
        *(__nv_bfloat162*)(base +  512) = l;
        *(__nv_bfloat162*)(base + 1024) = h;
    }
}

// ---------------------------------------------------------------------------
// helpers
// ---------------------------------------------------------------------------
#define BK     64
#define STAGES 3
#define A_ST   8192                   // 64 rows * 128B
#define B_ST   16384                  // 128 rows * 128B
#define ST_SZ  (A_ST + B_ST)          // 24KB per stage
#define DSMEM  (STAGES * ST_SZ)       // 72KB (drain phase needs 67.6KB <= this)
#define PSTR   132                    // padded fp32 row stride for drain tiles

__device__ __forceinline__ uint32_t s2u(const void* p) {
    return (uint32_t)__cvta_generic_to_shared(p);
}
#define CPA16(s, g) asm volatile("cp.async.cg.shared.global [%0], [%1], 16;" :: "r"(s), "l"(g))
#define LDSM4(r0,r1,r2,r3,a) asm volatile( \
    "ldmatrix.sync.aligned.m8n8.x4.shared.b16 {%0,%1,%2,%3}, [%4];" \
    : "=r"(r0),"=r"(r1),"=r"(r2),"=r"(r3) : "r"(a))
#define MMA16816(c,a0,a1,a2,a3,b0,b1) asm volatile( \
    "mma.sync.aligned.m16n8k16.row.col.f32.bf16.bf16.f32 " \
    "{%0,%1,%2,%3},{%4,%5,%6,%7},{%8,%9},{%0,%1,%2,%3};" \
    : "+f"(c[0]),"+f"(c[1]),"+f"(c[2]),"+f"(c[3]) \
    : "r"(a0),"r"(a1),"r"(a2),"r"(a3),"r"(b0),"r"(b1))

__device__ __forceinline__ uint32_t swz(uint32_t row, uint32_t cb) {
    return row * 128 + (cb ^ ((row & 7) * 16));
}
__device__ __forceinline__ void stcs(float4* p, float4 v) {
    asm volatile("st.global.cs.v4.f32 [%0], {%1,%2,%3,%4};"
                 :: "l"(p), "f"(v.x), "f"(v.y), "f"(v.z), "f"(v.w));
}
__device__ __forceinline__ void wait_flag(const int* f) {
    int v;
    while (true) {
        asm volatile("ld.acquire.gpu.global.b32 %0, [%1];" : "=r"(v) : "l"(f));
        if (v) break;
        __nanosleep(200);
    }
}

// ---------------------------------------------------------------------------
// Fused kernel: GEMM everywhere, output drain fused into enc epilogue.
// ---------------------------------------------------------------------------
__global__ __launch_bounds__(256, 2)
void fused_kernel(const float* __restrict__ bias, float* __restrict__ out) {
    extern __shared__ __align__(1024) char smem[];
    const uint32_t sb = s2u(smem);
    const int bid = blockIdx.x;
    const int tid = threadIdx.x;
    const int lane = tid & 31;
    const int wid  = tid >> 5;
    const int warp_m = wid & 1;     // 32 M rows
    const int warp_n = wid >> 1;    // 32 N cols

    const bool is_pred = (bid < 64);
    int m, n, b;
    const __nv_bfloat16 *gA, *gB;
    if (is_pred) {
        const int pb = bid >> 4; n = bid & 15;
        gA = g_Ac + (size_t)(1024 + pb * 64) * KC;
        gB = g_Bp + (size_t)(n * 128) * KC;
        m = pb;            // pred block index
        b = pb;
    } else {
        const int e = bid - 64;
        m = e >> 4; n = e & 15;
        gA = g_Ac + (size_t)(m * 64) * KC;
        gB = g_Be + (size_t)(n * 128) * KC;
        b = m >> 2;
    }
    const int vbase = n * 128;

    // ---- cp.async staging precompute (round-4 proven) ----
    const int ra0 = tid >> 3,         ja0 = (tid & 7) * 16;
    const int ra1 = (tid + 256) >> 3, ja1 = (tid & 7) * 16;
    const uint32_t sA0 = swz(ra0, ja0), sA1 = swz(ra1, ja1);
    int      rb[4], jb[4];
    uint32_t sB[4];
    #pragma unroll
    for (int i = 0; i < 4; i++) {
        int cidx = tid + i * 256;
        rb[i] = cidx >> 3; jb[i] = (cidx & 7) * 16;
        sB[i] = swz(rb[i], jb[i]);
    }

    const int rowA = warp_m * 32 + (lane & 15);
    const uint32_t uA = swz(rowA, (lane >> 4) * 16);
    const int rowB = warp_n * 32 + ((lane >> 4) & 1) * 8 + (lane & 7);
    const uint32_t uB = swz(rowB, ((lane >> 3) & 1) * 16);

    float c[2][4][4];
    #pragma unroll
    for (int i = 0; i < 2; i++)
        #pragma unroll
        for (int j = 0; j < 4; j++)
            #pragma unroll
            for (int e2 = 0; e2 < 4; e2++) c[i][j][e2] = 0.f;

    auto fill = [&](int s, int koff) {
        const uint32_t ab = sb + s * ST_SZ;
        const uint32_t bb = ab + A_ST;
        CPA16(ab + sA0, gA + (size_t)ra0 * KC + koff + ja0 / 2);
        CPA16(ab + sA1, gA + (size_t)ra1 * KC + koff + ja1 / 2);
        #pragma unroll
        for (int i = 0; i < 4; i++)
            CPA16(bb + sB[i], gB + (size_t)rb[i] * KC + koff + jb[i] / 2);
        asm volatile("cp.async.commit_group;");
    };

    fill(0, 0);
    fill(1, BK);

    const int NKT = KC / BK;   // 24
    int s = 0;
    for (int kt = 0; kt < NKT; kt++) {
        if (kt < NKT - 1) asm volatile("cp.async.wait_group 1;");
        else              asm volatile("cp.async.wait_group 0;");
        __syncthreads();

        if (kt + 2 < NKT) {
            int sn = s + 2; if (sn >= STAGES) sn -= STAGES;
            fill(sn, (kt + 2) * BK);
        }

        const uint32_t abase = sb + s * ST_SZ + uA;
        const uint32_t bbase = sb + s * ST_SZ + A_ST + uB;
        #pragma unroll
        for (int kk = 0; kk < 4; kk++) {
            uint32_t a[2][4], bfr[2][4];
            #pragma unroll
            for (int mi = 0; mi < 2; mi++)
                LDSM4(a[mi][0], a[mi][1], a[mi][2], a[mi][3],
                      (abase + mi * 2048) ^ (kk << 5));
            #pragma unroll
            for (int nb = 0; nb < 2; nb++)
                LDSM4(bfr[nb][0], bfr[nb][1], bfr[nb][2], bfr[nb][3],
                      (bbase + nb * 2048) ^ (kk << 5));
            #pragma unroll
            for (int mi = 0; mi < 2; mi++) {
                MMA16816(c[mi][0], a[mi][0], a[mi][1], a[mi][2], a[mi][3], bfr[0][0], bfr[0][1]);
                MMA16816(c[mi][1], a[mi][0], a[mi][1], a[mi][2], a[mi][3], bfr[0][2], bfr[0][3]);
                MMA16816(c[mi][2], a[mi][0], a[mi][1], a[mi][2], a[mi][3], bfr[1][0], bfr[1][1]);
                MMA16816(c[mi][3], a[mi][0], a[mi][1], a[mi][2], a[mi][3], bfr[1][2], bfr[1][3]);
            }
        }
        if (++s >= STAGES) s -= STAGES;
    }

    const int mrow0 = warp_m * 32 + (lane >> 2);
    const int ncol0 = warp_n * 32 + (lane & 3) * 2;

    if (is_pred) {
        // ---- pred epilogue: frags -> g_pred, then release flag ----
        float* C = g_pred + (size_t)(m * 64) * VOCAB + vbase;
        #pragma unroll
        for (int mi = 0; mi < 2; mi++) {
            #pragma unroll
            for (int ni = 0; ni < 4; ni++) {
                float* p0 = &C[(size_t)(mrow0 + mi * 16)     * VOCAB + ncol0 + ni * 8];
                float* p1 = &C[(size_t)(mrow0 + mi * 16 + 8) * VOCAB + ncol0 + ni * 8];
                *(float2*)p0 = make_float2(c[mi][ni][0], c[mi][ni][1]);
                *(float2*)p1 = make_float2(c[mi][ni][2], c[mi][ni][3]);
            }
        }
        __threadfence();
        __syncthreads();
        if (tid == 0) atomicExch(&g_flags[bid], 1);
        return;
    }

    // ---- enc epilogue: frags -> smem, fetch pred tile, drain output ----
    __syncthreads();                       // all LDSM done; safe to reuse smem
    float* enc_s  = (float*)smem;          // [64][PSTR]
    float* pred_s = enc_s + 64 * PSTR;     // [64][PSTR]

    #pragma unroll
    for (int mi = 0; mi < 2; mi++) {
        #pragma unroll
        for (int ni = 0; ni < 4; ni++) {
            float* p0 = &enc_s[(mrow0 + mi * 16)     * PSTR + ncol0 + ni * 8];
            float* p1 = &enc_s[(mrow0 + mi * 16 + 8) * PSTR + ncol0 + ni * 8];
            *(float2*)p0 = make_float2(c[mi][ni][0], c[mi][ni][1]);
            *(float2*)p1 = make_float2(c[mi][ni][2], c[mi][ni][3]);
        }
    }

    if (tid == 0) wait_flag(&g_flags[b * 16 + n]);
    __syncthreads();

    // pred tile + bias -> smem: 64u x 128v = 2048 float4, 8/thread
    {
        const float* pg = g_pred + (size_t)(b * NU) * VOCAB + vbase;
        #pragma unroll
        for (int i = 0; i < 8; i++) {
            int e = tid + i * 256;
            int u = e >> 5, cc = e & 31;
            float4 p = *(const float4*)(pg + (size_t)u * VOCAB + cc * 4);
            float4 bv = *(const float4*)(bias + vbase + cc * 4);
            *(float4*)&pred_s[u * PSTR + cc * 4] =
                make_float4(p.x + bv.x, p.y + bv.y, p.z + bv.z, p.w + bv.w);
        }
    }
    __syncthreads();

    // drain: warp w handles t rows [w*8, w*8+8); per (t,u) row a full warp
    // stores 128 contiguous floats (512B, coalesced).
    const int col   = lane;                // float4 col 0..31
    const int tbase = (m & 3) * 64;
    float* ob = out + ((size_t)(b * NT + tbase) * NU) * VOCAB + vbase;

    #pragma unroll
    for (int ti = 0; ti < 8; ti++) {
        const int t = wid * 8 + ti;
        float4 e = *(float4*)&enc_s[t * PSTR + col * 4];
        float4* orow = (float4*)(ob + (size_t)t * NU * VOCAB);
        #pragma unroll 8
        for (int u = 0; u < NU; u++) {
            float4 p = *(float4*)&pred_s[u * PSTR + col * 4];
            stcs(&orow[u * (VOCAB / 4) + col],
                 make_float4(e.x + p.x, e.y + p.y, e.z + p.z, e.w + p.w));
        }
    }
}

// ---------------------------------------------------------------------------
extern "C" void kernel_launch(void* const* d_in, const int* in_sizes, int n_in,
                              void* d_out, int out_size) {
    const float* enc  = (const float*)d_in[0];
    const float* pred = (const float*)d_in[1];
    const float* W    = (const float*)d_in[2];
    const float* bias = (const float*)d_in[3];
    float* out = (float*)d_out;

    cudaFuncSetAttribute(fused_kernel,
                         cudaFuncAttributeMaxDynamicSharedMemorySize, DSMEM);

    convert_kernel<<<5376, 256>>>(enc, pred, W);
    fused_kernel<<<320, 256, DSMEM>>>(bias, out);
}